// round 11
// baseline (speedup 1.0000x reference)
#include <cuda_runtime.h>

#define NUM_USERS 100000
#define NUM_ITEMS 50000
#define NUM_EDGES 1000000
#define EMB 64

// Scratch (static device globals — no runtime allocation allowed)
__device__ __align__(16) float g_acc_u[NUM_USERS * EMB];   // 25.6 MB
__device__ __align__(16) float g_acc_i[NUM_ITEMS * EMB];   // 12.8 MB
__device__ __align__(16) float g_u1[NUM_USERS * EMB];      // round-1 user output
__device__ __align__(16) float g_i1[NUM_ITEMS * EMB];      // round-1 item output
__device__ int g_deg_u[NUM_USERS];
__device__ int g_deg_i[NUM_ITEMS];

__device__ __forceinline__ void red_add4(float* p, float4 v) {
    asm volatile("red.global.add.v4.f32 [%0], {%1, %2, %3, %4};"
                 :: "l"(p), "f"(v.x), "f"(v.y), "f"(v.z), "f"(v.w) : "memory");
}

// Each HALF-WARP (16 lanes) covers one edge: 16 lanes x float4 = 64 floats.
// Each half-warp processes 2 edges; all 4 gathers (2 edges x 2 directions)
// are issued BEFORE any reduction so the LDG.128s overlap (MLP >= 4).
template<bool COUNT_DEG>
__global__ void scatter_kernel(const float4* __restrict__ usrc,
                               const float4* __restrict__ isrc,
                               const int*   __restrict__ es,
                               const int*   __restrict__ ed) {
    unsigned gtid = blockIdx.x * blockDim.x + threadIdx.x;
    unsigned hw   = gtid >> 4;            // global half-warp id
    unsigned sub  = threadIdx.x & 15;     // lane within half-warp

    unsigned e0 = hw * 2;                 // two edges per half-warp
    unsigned e1 = e0 + 1;
    if (e0 >= NUM_EDGES) return;

    int s0 = __ldg(es + e0);
    int d0 = __ldg(ed + e0);
    int s1 = __ldg(es + e1);
    int d1 = __ldg(ed + e1);

    // Batch all gathers first (independent LDG.128s in flight)
    float4 uv0 = __ldg(usrc + (size_t)s0 * 16 + sub);
    float4 iv0 = __ldg(isrc + (size_t)d0 * 16 + sub);
    float4 uv1 = __ldg(usrc + (size_t)s1 * 16 + sub);
    float4 iv1 = __ldg(isrc + (size_t)d1 * 16 + sub);

    // Then the vector reductions
    red_add4(g_acc_i + (size_t)d0 * EMB + 4u * sub, uv0);
    red_add4(g_acc_u + (size_t)s0 * EMB + 4u * sub, iv0);
    red_add4(g_acc_i + (size_t)d1 * EMB + 4u * sub, uv1);
    red_add4(g_acc_u + (size_t)s1 * EMB + 4u * sub, iv1);

    if (COUNT_DEG && sub == 0) {
        atomicAdd(&g_deg_i[d0], 1);
        atomicAdd(&g_deg_u[s0], 1);
        atomicAdd(&g_deg_i[d1], 1);
        atomicAdd(&g_deg_u[s1], 1);
    }
}

// out = acc * inv_deg + emb * sw   (per row), vectorized float4.
// RESET zeroes the accumulator for the next round.
template<bool RESET>
__global__ void combine_kernel(float* __restrict__ acc,
                               const float* __restrict__ emb,
                               const float* __restrict__ sw,
                               const int*   __restrict__ deg,
                               float* __restrict__ out,
                               int n_rows) {
    unsigned idx = blockIdx.x * blockDim.x + threadIdx.x;   // float4 index
    unsigned total = (unsigned)n_rows * (EMB / 4);
    if (idx >= total) return;
    unsigned row = idx >> 4;   // 16 float4 per row

    int dg = __ldg(deg + row);
    float inv = dg > 0 ? 1.0f / (float)dg : 0.0f;
    float s = __ldg(sw + row);

    float4 a   = __ldg((const float4*)acc + idx);
    float4 ebv = __ldg((const float4*)emb + idx);
    float4 o;
    o.x = a.x * inv + ebv.x * s;
    o.y = a.y * inv + ebv.y * s;
    o.z = a.z * inv + ebv.z * s;
    o.w = a.w * inv + ebv.w * s;
    ((float4*)out)[idx] = o;

    if (RESET) {
        ((float4*)acc)[idx] = make_float4(0.f, 0.f, 0.f, 0.f);
    }
}

extern "C" void kernel_launch(void* const* d_in, const int* in_sizes, int n_in,
                              void* d_out, int out_size) {
    const float* user_emb = (const float*)d_in[0];
    const float* item_emb = (const float*)d_in[1];
    const float* u_sw     = (const float*)d_in[2];
    const float* i_sw     = (const float*)d_in[3];
    const int*   es       = (const int*)d_in[4];
    const int*   ed       = (const int*)d_in[5];
    float* out = (float*)d_out;

    float *acc_u, *acc_i, *u1, *i1;
    int *deg_u, *deg_i;
    cudaGetSymbolAddress((void**)&acc_u, g_acc_u);
    cudaGetSymbolAddress((void**)&acc_i, g_acc_i);
    cudaGetSymbolAddress((void**)&u1,    g_u1);
    cudaGetSymbolAddress((void**)&i1,    g_i1);
    cudaGetSymbolAddress((void**)&deg_u, g_deg_u);
    cudaGetSymbolAddress((void**)&deg_i, g_deg_i);

    // Zero accumulators + degree counters (graph-capturable memset nodes)
    cudaMemsetAsync(acc_u, 0, sizeof(float) * NUM_USERS * EMB, 0);
    cudaMemsetAsync(acc_i, 0, sizeof(float) * NUM_ITEMS * EMB, 0);
    cudaMemsetAsync(deg_u, 0, sizeof(int) * NUM_USERS, 0);
    cudaMemsetAsync(deg_i, 0, sizeof(int) * NUM_ITEMS, 0);

    // Half-warp per edge, 2 edges per half-warp: 16 threads cover 2 edges.
    const int SBLK = 256;
    const long long total_threads = (long long)(NUM_EDGES / 2) * 16;
    const int sgrid = (int)((total_threads + SBLK - 1) / SBLK);

    // ---- Round 1 ----
    scatter_kernel<true><<<sgrid, SBLK>>>((const float4*)user_emb,
                                          (const float4*)item_emb, es, ed);

    const int CBLK = 256;
    int ugrid = (NUM_USERS * (EMB / 4) + CBLK - 1) / CBLK;
    int igrid = (NUM_ITEMS * (EMB / 4) + CBLK - 1) / CBLK;
    combine_kernel<true><<<ugrid, CBLK>>>(acc_u, user_emb, u_sw, deg_u, u1, NUM_USERS);
    combine_kernel<true><<<igrid, CBLK>>>(acc_i, item_emb, i_sw, deg_i, i1, NUM_ITEMS);

    // ---- Round 2 ----
    scatter_kernel<false><<<sgrid, SBLK>>>((const float4*)u1, (const float4*)i1, es, ed);

    combine_kernel<false><<<ugrid, CBLK>>>(acc_u, u1, u_sw, deg_u, out, NUM_USERS);
    combine_kernel<false><<<igrid, CBLK>>>(acc_i, i1, i_sw, deg_i,
                                           out + (size_t)NUM_USERS * EMB, NUM_ITEMS);
}

// round 12
// speedup vs baseline: 1.0010x; 1.0010x over previous
#include <cuda_runtime.h>

#define NUM_USERS 100000
#define NUM_ITEMS 50000
#define NUM_EDGES 1000000
#define EMB 64

// Scratch (static device globals — no runtime allocation allowed)
__device__ __align__(16) float g_acc_u[NUM_USERS * EMB];   // 25.6 MB
__device__ __align__(16) float g_acc_i[NUM_ITEMS * EMB];   // 12.8 MB
__device__ __align__(16) float g_u1[NUM_USERS * EMB];      // round-1 user output
__device__ __align__(16) float g_i1[NUM_ITEMS * EMB];      // round-1 item output
__device__ int g_deg_u[NUM_USERS];
__device__ int g_deg_i[NUM_ITEMS];

__device__ __forceinline__ void red_add4(float* p, float4 v) {
    asm volatile("red.global.add.v4.f32 [%0], {%1, %2, %3, %4};"
                 :: "l"(p), "f"(v.x), "f"(v.y), "f"(v.z), "f"(v.w) : "memory");
}

// Each HALF-WARP (16 lanes) covers one edge: 16 lanes x float4 = 64 floats.
// Each half-warp processes 2 edges; all 4 gathers (2 edges x 2 directions)
// are issued BEFORE any reduction so the LDG.128s overlap (MLP >= 4).
template<bool COUNT_DEG>
__global__ void scatter_kernel(const float4* __restrict__ usrc,
                               const float4* __restrict__ isrc,
                               const int*   __restrict__ es,
                               const int*   __restrict__ ed) {
    unsigned gtid = blockIdx.x * blockDim.x + threadIdx.x;
    unsigned hw   = gtid >> 4;            // global half-warp id
    unsigned sub  = threadIdx.x & 15;     // lane within half-warp

    unsigned e0 = hw * 2;                 // two edges per half-warp
    unsigned e1 = e0 + 1;
    if (e0 >= NUM_EDGES) return;

    int s0 = __ldg(es + e0);
    int d0 = __ldg(ed + e0);
    int s1 = __ldg(es + e1);
    int d1 = __ldg(ed + e1);

    // Batch all gathers first (independent LDG.128s in flight)
    float4 uv0 = __ldg(usrc + (size_t)s0 * 16 + sub);
    float4 iv0 = __ldg(isrc + (size_t)d0 * 16 + sub);
    float4 uv1 = __ldg(usrc + (size_t)s1 * 16 + sub);
    float4 iv1 = __ldg(isrc + (size_t)d1 * 16 + sub);

    // Then the vector reductions
    red_add4(g_acc_i + (size_t)d0 * EMB + 4u * sub, uv0);
    red_add4(g_acc_u + (size_t)s0 * EMB + 4u * sub, iv0);
    red_add4(g_acc_i + (size_t)d1 * EMB + 4u * sub, uv1);
    red_add4(g_acc_u + (size_t)s1 * EMB + 4u * sub, iv1);

    if (COUNT_DEG && sub == 0) {
        atomicAdd(&g_deg_i[d0], 1);
        atomicAdd(&g_deg_u[s0], 1);
        atomicAdd(&g_deg_i[d1], 1);
        atomicAdd(&g_deg_u[s1], 1);
    }
}

// out = acc * inv_deg + emb * sw   (per row), vectorized float4.
// RESET zeroes the accumulator for the next round.
template<bool RESET>
__global__ void combine_kernel(float* __restrict__ acc,
                               const float* __restrict__ emb,
                               const float* __restrict__ sw,
                               const int*   __restrict__ deg,
                               float* __restrict__ out,
                               int n_rows) {
    unsigned idx = blockIdx.x * blockDim.x + threadIdx.x;   // float4 index
    unsigned total = (unsigned)n_rows * (EMB / 4);
    if (idx >= total) return;
    unsigned row = idx >> 4;   // 16 float4 per row

    int dg = __ldg(deg + row);
    float inv = dg > 0 ? 1.0f / (float)dg : 0.0f;
    float s = __ldg(sw + row);

    float4 a   = __ldg((const float4*)acc + idx);
    float4 ebv = __ldg((const float4*)emb + idx);
    float4 o;
    o.x = a.x * inv + ebv.x * s;
    o.y = a.y * inv + ebv.y * s;
    o.z = a.z * inv + ebv.z * s;
    o.w = a.w * inv + ebv.w * s;
    ((float4*)out)[idx] = o;

    if (RESET) {
        ((float4*)acc)[idx] = make_float4(0.f, 0.f, 0.f, 0.f);
    }
}

extern "C" void kernel_launch(void* const* d_in, const int* in_sizes, int n_in,
                              void* d_out, int out_size) {
    const float* user_emb = (const float*)d_in[0];
    const float* item_emb = (const float*)d_in[1];
    const float* u_sw     = (const float*)d_in[2];
    const float* i_sw     = (const float*)d_in[3];
    const int*   es       = (const int*)d_in[4];
    const int*   ed       = (const int*)d_in[5];
    float* out = (float*)d_out;

    float *acc_u, *acc_i, *u1, *i1;
    int *deg_u, *deg_i;
    cudaGetSymbolAddress((void**)&acc_u, g_acc_u);
    cudaGetSymbolAddress((void**)&acc_i, g_acc_i);
    cudaGetSymbolAddress((void**)&u1,    g_u1);
    cudaGetSymbolAddress((void**)&i1,    g_i1);
    cudaGetSymbolAddress((void**)&deg_u, g_deg_u);
    cudaGetSymbolAddress((void**)&deg_i, g_deg_i);

    // Zero accumulators + degree counters (graph-capturable memset nodes)
    cudaMemsetAsync(acc_u, 0, sizeof(float) * NUM_USERS * EMB, 0);
    cudaMemsetAsync(acc_i, 0, sizeof(float) * NUM_ITEMS * EMB, 0);
    cudaMemsetAsync(deg_u, 0, sizeof(int) * NUM_USERS, 0);
    cudaMemsetAsync(deg_i, 0, sizeof(int) * NUM_ITEMS, 0);

    // Half-warp per edge, 2 edges per half-warp: 16 threads cover 2 edges.
    const int SBLK = 256;
    const long long total_threads = (long long)(NUM_EDGES / 2) * 16;
    const int sgrid = (int)((total_threads + SBLK - 1) / SBLK);

    // ---- Round 1 ----
    scatter_kernel<true><<<sgrid, SBLK>>>((const float4*)user_emb,
                                          (const float4*)item_emb, es, ed);

    const int CBLK = 256;
    int ugrid = (NUM_USERS * (EMB / 4) + CBLK - 1) / CBLK;
    int igrid = (NUM_ITEMS * (EMB / 4) + CBLK - 1) / CBLK;
    combine_kernel<true><<<ugrid, CBLK>>>(acc_u, user_emb, u_sw, deg_u, u1, NUM_USERS);
    combine_kernel<true><<<igrid, CBLK>>>(acc_i, item_emb, i_sw, deg_i, i1, NUM_ITEMS);

    // ---- Round 2 ----
    scatter_kernel<false><<<sgrid, SBLK>>>((const float4*)u1, (const float4*)i1, es, ed);

    combine_kernel<false><<<ugrid, CBLK>>>(acc_u, u1, u_sw, deg_u, out, NUM_USERS);
    combine_kernel<false><<<igrid, CBLK>>>(acc_i, i1, i_sw, deg_i,
                                           out + (size_t)NUM_USERS * EMB, NUM_ITEMS);
}

// round 13
// speedup vs baseline: 1.0028x; 1.0018x over previous
#include <cuda_runtime.h>

#define NUM_USERS 100000
#define NUM_ITEMS 50000
#define NUM_EDGES 1000000
#define EMB 64

// Scratch (static device globals — no runtime allocation allowed)
__device__ __align__(16) float g_acc_u[NUM_USERS * EMB];   // 25.6 MB
__device__ __align__(16) float g_acc_i[NUM_ITEMS * EMB];   // 12.8 MB
__device__ __align__(16) float g_u1[NUM_USERS * EMB];      // round-1 user output
__device__ __align__(16) float g_i1[NUM_ITEMS * EMB];      // round-1 item output
__device__ int g_deg_u[NUM_USERS];
__device__ int g_deg_i[NUM_ITEMS];

__device__ __forceinline__ void red_add4(float* p, float4 v) {
    asm volatile("red.global.add.v4.f32 [%0], {%1, %2, %3, %4};"
                 :: "l"(p), "f"(v.x), "f"(v.y), "f"(v.z), "f"(v.w) : "memory");
}

// Each HALF-WARP (16 lanes) covers one edge: 16 lanes x float4 = 64 floats.
// Each half-warp processes 2 edges; all 4 gathers (2 edges x 2 directions)
// are issued BEFORE any reduction so the LDG.128s overlap (MLP >= 4).
template<bool COUNT_DEG>
__global__ void scatter_kernel(const float4* __restrict__ usrc,
                               const float4* __restrict__ isrc,
                               const int*   __restrict__ es,
                               const int*   __restrict__ ed) {
    unsigned gtid = blockIdx.x * blockDim.x + threadIdx.x;
    unsigned hw   = gtid >> 4;            // global half-warp id
    unsigned sub  = threadIdx.x & 15;     // lane within half-warp

    unsigned e0 = hw * 2;                 // two edges per half-warp
    unsigned e1 = e0 + 1;
    if (e0 >= NUM_EDGES) return;

    int s0 = __ldg(es + e0);
    int d0 = __ldg(ed + e0);
    int s1 = __ldg(es + e1);
    int d1 = __ldg(ed + e1);

    // Batch all gathers first (independent LDG.128s in flight)
    float4 uv0 = __ldg(usrc + (size_t)s0 * 16 + sub);
    float4 iv0 = __ldg(isrc + (size_t)d0 * 16 + sub);
    float4 uv1 = __ldg(usrc + (size_t)s1 * 16 + sub);
    float4 iv1 = __ldg(isrc + (size_t)d1 * 16 + sub);

    // Then the vector reductions
    red_add4(g_acc_i + (size_t)d0 * EMB + 4u * sub, uv0);
    red_add4(g_acc_u + (size_t)s0 * EMB + 4u * sub, iv0);
    red_add4(g_acc_i + (size_t)d1 * EMB + 4u * sub, uv1);
    red_add4(g_acc_u + (size_t)s1 * EMB + 4u * sub, iv1);

    if (COUNT_DEG && sub == 0) {
        atomicAdd(&g_deg_i[d0], 1);
        atomicAdd(&g_deg_u[s0], 1);
        atomicAdd(&g_deg_i[d1], 1);
        atomicAdd(&g_deg_u[s1], 1);
    }
}

// out = acc * inv_deg + emb * sw   (per row), vectorized float4.
// RESET zeroes the accumulator for the next round.
template<bool RESET>
__global__ void combine_kernel(float* __restrict__ acc,
                               const float* __restrict__ emb,
                               const float* __restrict__ sw,
                               const int*   __restrict__ deg,
                               float* __restrict__ out,
                               int n_rows) {
    unsigned idx = blockIdx.x * blockDim.x + threadIdx.x;   // float4 index
    unsigned total = (unsigned)n_rows * (EMB / 4);
    if (idx >= total) return;
    unsigned row = idx >> 4;   // 16 float4 per row

    int dg = __ldg(deg + row);
    float inv = dg > 0 ? 1.0f / (float)dg : 0.0f;
    float s = __ldg(sw + row);

    float4 a   = __ldg((const float4*)acc + idx);
    float4 ebv = __ldg((const float4*)emb + idx);
    float4 o;
    o.x = a.x * inv + ebv.x * s;
    o.y = a.y * inv + ebv.y * s;
    o.z = a.z * inv + ebv.z * s;
    o.w = a.w * inv + ebv.w * s;
    ((float4*)out)[idx] = o;

    if (RESET) {
        ((float4*)acc)[idx] = make_float4(0.f, 0.f, 0.f, 0.f);
    }
}

extern "C" void kernel_launch(void* const* d_in, const int* in_sizes, int n_in,
                              void* d_out, int out_size) {
    const float* user_emb = (const float*)d_in[0];
    const float* item_emb = (const float*)d_in[1];
    const float* u_sw     = (const float*)d_in[2];
    const float* i_sw     = (const float*)d_in[3];
    const int*   es       = (const int*)d_in[4];
    const int*   ed       = (const int*)d_in[5];
    float* out = (float*)d_out;

    float *acc_u, *acc_i, *u1, *i1;
    int *deg_u, *deg_i;
    cudaGetSymbolAddress((void**)&acc_u, g_acc_u);
    cudaGetSymbolAddress((void**)&acc_i, g_acc_i);
    cudaGetSymbolAddress((void**)&u1,    g_u1);
    cudaGetSymbolAddress((void**)&i1,    g_i1);
    cudaGetSymbolAddress((void**)&deg_u, g_deg_u);
    cudaGetSymbolAddress((void**)&deg_i, g_deg_i);

    // Zero accumulators + degree counters (graph-capturable memset nodes)
    cudaMemsetAsync(acc_u, 0, sizeof(float) * NUM_USERS * EMB, 0);
    cudaMemsetAsync(acc_i, 0, sizeof(float) * NUM_ITEMS * EMB, 0);
    cudaMemsetAsync(deg_u, 0, sizeof(int) * NUM_USERS, 0);
    cudaMemsetAsync(deg_i, 0, sizeof(int) * NUM_ITEMS, 0);

    // Half-warp per edge, 2 edges per half-warp: 16 threads cover 2 edges.
    const int SBLK = 256;
    const long long total_threads = (long long)(NUM_EDGES / 2) * 16;
    const int sgrid = (int)((total_threads + SBLK - 1) / SBLK);

    // ---- Round 1 ----
    scatter_kernel<true><<<sgrid, SBLK>>>((const float4*)user_emb,
                                          (const float4*)item_emb, es, ed);

    const int CBLK = 256;
    int ugrid = (NUM_USERS * (EMB / 4) + CBLK - 1) / CBLK;
    int igrid = (NUM_ITEMS * (EMB / 4) + CBLK - 1) / CBLK;
    combine_kernel<true><<<ugrid, CBLK>>>(acc_u, user_emb, u_sw, deg_u, u1, NUM_USERS);
    combine_kernel<true><<<igrid, CBLK>>>(acc_i, item_emb, i_sw, deg_i, i1, NUM_ITEMS);

    // ---- Round 2 ----
    scatter_kernel<false><<<sgrid, SBLK>>>((const float4*)u1, (const float4*)i1, es, ed);

    combine_kernel<false><<<ugrid, CBLK>>>(acc_u, u1, u_sw, deg_u, out, NUM_USERS);
    combine_kernel<false><<<igrid, CBLK>>>(acc_i, i1, i_sw, deg_i,
                                           out + (size_t)NUM_USERS * EMB, NUM_ITEMS);
}